// round 1
// baseline (speedup 1.0000x reference)
#include <cuda_runtime.h>
#include <math.h>

#define NTOK   343
#define NHEADS 6
#define HD     32
#define CDIM   192
#define MROWS  43904   // 128 windows * 343 tokens
#define LTOK   21952

// ---------------- scratch (static device arrays; no allocation) ----------------
__device__ float d_q[8429568];
__device__ float d_k[8429568];
__device__ float d_v[8429568];
__device__ float d_hb[2197 * 6];
__device__ float d_rpb[6 * NTOK * NTOK];
__device__ float d_attn[MROWS * CDIM];
__device__ float d_tmp[MROWS * CDIM];
__device__ float d_x1[MROWS * CDIM];
__device__ float d_hid[MROWS * 768];

// -------- helpers --------
__device__ __forceinline__ int regcls(int c) { return c < 21 ? 0 : (c < 25 ? 1 : 2); }

__device__ __forceinline__ float cpb_coord(int i) {
    float x = (float)(i - 6) * (8.0f / 6.0f);
    return copysignf(log2f(fabsf(x) + 1.0f) * (1.0f / 3.0f), x);
}

// map window-token row m -> source/destination token row in [B, L]
// (roll by -3 then window partition on input; same map applies to output since
//  window_reverse followed by roll +3 is the exact inverse arrangement)
__device__ __forceinline__ int gather_row(int m) {
    int b_ = m / 343;  int n = m - b_ * 343;
    int b  = b_ >> 6;  int widx = b_ & 63;
    int th = n / 49;   int rem = n - th * 49;
    int tw = rem / 7;  int td = rem - tw * 7;
    int hh = ((widx >> 4) * 7 + th + 3) % 28;
    int wc = (((widx >> 2) & 3) * 7 + tw + 3) % 28;
    int dc = ((widx & 3) * 7 + td + 3) % 28;
    return b * LTOK + (hh * 28 + wc) * 28 + dc;
}

// ---------------- CPB MLP: hb[2197][6] ----------------
__global__ void __launch_bounds__(256) cpb_kernel(const float* __restrict__ w1,
                                                  const float* __restrict__ b1,
                                                  const float* __restrict__ w2) {
    int row = blockIdx.x * 8 + (threadIdx.x >> 5);
    if (row >= 2197) return;
    int lane = threadIdx.x & 31;
    int dh = row / 169; int rem = row - dh * 169;
    int dw = rem / 13;  int dd = rem - dw * 13;
    float c0 = cpb_coord(dh), c1 = cpb_coord(dw), c2 = cpb_coord(dd);
    float a0 = 0, a1 = 0, a2 = 0, a3 = 0, a4 = 0, a5 = 0;
    for (int i = lane; i < 512; i += 32) {
        float hv = c0 * w1[i * 3] + c1 * w1[i * 3 + 1] + c2 * w1[i * 3 + 2] + b1[i];
        hv = fmaxf(hv, 0.0f);
        a0 = fmaf(hv, w2[i], a0);
        a1 = fmaf(hv, w2[512 + i], a1);
        a2 = fmaf(hv, w2[1024 + i], a2);
        a3 = fmaf(hv, w2[1536 + i], a3);
        a4 = fmaf(hv, w2[2048 + i], a4);
        a5 = fmaf(hv, w2[2560 + i], a5);
    }
    #pragma unroll
    for (int o = 16; o; o >>= 1) {
        a0 += __shfl_xor_sync(0xffffffffu, a0, o);
        a1 += __shfl_xor_sync(0xffffffffu, a1, o);
        a2 += __shfl_xor_sync(0xffffffffu, a2, o);
        a3 += __shfl_xor_sync(0xffffffffu, a3, o);
        a4 += __shfl_xor_sync(0xffffffffu, a4, o);
        a5 += __shfl_xor_sync(0xffffffffu, a5, o);
    }
    if (lane == 0) {
        d_hb[row * 6 + 0] = a0; d_hb[row * 6 + 1] = a1; d_hb[row * 6 + 2] = a2;
        d_hb[row * 6 + 3] = a3; d_hb[row * 6 + 4] = a4; d_hb[row * 6 + 5] = a5;
    }
}

// ---------------- expand rpb[h][i][j] = 16*sigmoid(hb[rpi(i,j)][h]) ----------------
__global__ void __launch_bounds__(256) rpb_kernel() {
    int g = blockIdx.x * 256 + threadIdx.x;
    if (g >= 6 * NTOK * NTOK) return;
    int h = g / (NTOK * NTOK); int rem = g - h * NTOK * NTOK;
    int i = rem / NTOK; int j = rem - i * NTOK;
    int ih = i / 49, iw = (i / 7) % 7, id = i % 7;
    int jh = j / 49, jw = (j / 7) % 7, jd = j % 7;
    int idx = (ih - jh + 6) * 169 + (iw - jw + 6) * 13 + (id - jd + 6);
    float x = d_hb[idx * 6 + h];
    d_rpb[g] = 16.0f / (1.0f + expf(-x));
}

// ---------------- tiled GEMM: C[m,n] = A[m,:] . W[n,:] (+ epilogues) ----------------
// EPI: 0 = +bias store, 1 = +bias GELU store, 2 = qkv scatter (q/k/v + q/v bias)
template <bool GATHER, int EPI>
__global__ void __launch_bounds__(256) gemm_k(const float* __restrict__ A,
                                              const float* __restrict__ W,
                                              const float* __restrict__ bias,
                                              float* __restrict__ C,
                                              int K, int Nout,
                                              const float* __restrict__ qb,
                                              const float* __restrict__ vb) {
    __shared__ __align__(16) float As[16][68];
    __shared__ __align__(16) float Bs[16][68];
    int t = threadIdx.x;
    int n0 = blockIdx.x * 64, m0 = blockIdx.y * 64;
    int lr = t >> 2, lk = (t & 3) * 4;
    const float* aptr;
    if (GATHER) aptr = A + (size_t)gather_row(m0 + lr) * K + lk;
    else        aptr = A + (size_t)(m0 + lr) * K + lk;
    const float* bptr = W + (size_t)(n0 + lr) * K + lk;
    int tm = (t >> 4) * 4, tn = (t & 15) * 4;
    float acc[4][4];
    #pragma unroll
    for (int i = 0; i < 4; i++)
        #pragma unroll
        for (int j = 0; j < 4; j++) acc[i][j] = 0.0f;

    for (int k0 = 0; k0 < K; k0 += 16) {
        float4 a4 = *(const float4*)(aptr + k0);
        float4 b4 = *(const float4*)(bptr + k0);
        __syncthreads();
        As[lk + 0][lr] = a4.x; As[lk + 1][lr] = a4.y; As[lk + 2][lr] = a4.z; As[lk + 3][lr] = a4.w;
        Bs[lk + 0][lr] = b4.x; Bs[lk + 1][lr] = b4.y; Bs[lk + 2][lr] = b4.z; Bs[lk + 3][lr] = b4.w;
        __syncthreads();
        #pragma unroll
        for (int kk = 0; kk < 16; kk++) {
            float4 af = *(const float4*)&As[kk][tm];
            float4 bf = *(const float4*)&Bs[kk][tn];
            acc[0][0] = fmaf(af.x, bf.x, acc[0][0]); acc[0][1] = fmaf(af.x, bf.y, acc[0][1]);
            acc[0][2] = fmaf(af.x, bf.z, acc[0][2]); acc[0][3] = fmaf(af.x, bf.w, acc[0][3]);
            acc[1][0] = fmaf(af.y, bf.x, acc[1][0]); acc[1][1] = fmaf(af.y, bf.y, acc[1][1]);
            acc[1][2] = fmaf(af.y, bf.z, acc[1][2]); acc[1][3] = fmaf(af.y, bf.w, acc[1][3]);
            acc[2][0] = fmaf(af.z, bf.x, acc[2][0]); acc[2][1] = fmaf(af.z, bf.y, acc[2][1]);
            acc[2][2] = fmaf(af.z, bf.z, acc[2][2]); acc[2][3] = fmaf(af.z, bf.w, acc[2][3]);
            acc[3][0] = fmaf(af.w, bf.x, acc[3][0]); acc[3][1] = fmaf(af.w, bf.y, acc[3][1]);
            acc[3][2] = fmaf(af.w, bf.z, acc[3][2]); acc[3][3] = fmaf(af.w, bf.w, acc[3][3]);
        }
    }

    #pragma unroll
    for (int i = 0; i < 4; i++) {
        int mm = m0 + tm + i;
        #pragma unroll
        for (int j = 0; j < 4; j++) {
            int nn = n0 + tn + j;
            float v = acc[i][j];
            if (EPI == 0) {
                C[(size_t)mm * Nout + nn] = v + bias[nn];
            } else if (EPI == 1) {
                v += bias[nn];
                C[(size_t)mm * Nout + nn] = 0.5f * v * (1.0f + erff(v * 0.70710678f));
            } else {
                int sec = nn / 192; int cc = nn - sec * 192;
                float bv = (sec == 0) ? qb[cc] : (sec == 2 ? vb[cc] : 0.0f);
                v += bv;
                int b_ = mm / 343; int n = mm - b_ * 343;
                int head = cc >> 5; int dd = cc & 31;
                size_t dst = ((size_t)(b_ * 6 + head) * 343 + n) * 32 + dd;
                if (sec == 0) d_q[dst] = v;
                else if (sec == 1) d_k[dst] = v;
                else d_v[dst] = v;
            }
        }
    }
}

// ---------------- attention: one block per (window, head) ----------------
__global__ void __launch_bounds__(256) attn_kernel(const float* __restrict__ logit_scale) {
    extern __shared__ float sm[];
    float* kT  = sm;             // [32][343] normalized k, transposed
    float* vs  = sm + 10976;     // [343][32]
    float* scb = sm + 21952;     // 8 warps * [343][4] scores
    float* qTb = sm + 32928;     // 8 warps * [32][4] q rows (transposed)
    int*   rv  = (int*)(sm + 33952);  // [343] region label

    int bh = blockIdx.x;
    int b_ = bh / 6, h = bh - b_ * 6;
    int t = threadIdx.x, w = t >> 5, lane = t & 31;
    size_t base = (size_t)(b_ * 6 + h) * NTOK * HD;

    for (int i = t; i < NTOK * HD; i += 256) vs[i] = d_v[base + i];

    for (int j = w; j < NTOK; j += 8) {
        float kv = d_k[base + j * 32 + lane];
        float ss = kv * kv;
        #pragma unroll
        for (int o = 16; o; o >>= 1) ss += __shfl_xor_sync(0xffffffffu, ss, o);
        kT[lane * NTOK + j] = kv * (1.0f / fmaxf(sqrtf(ss), 1e-12f));
    }

    int widx = b_ & 63;
    int wh = widx >> 4, ww = (widx >> 2) & 3, wd = widx & 3;
    for (int n = t; n < NTOK; n += 256) {
        int th = n / 49; int rem = n - th * 49;
        int tw = rem / 7; int td = rem - tw * 7;
        rv[n] = regcls(wh * 7 + th) * 9 + regcls(ww * 7 + tw) * 3 + regcls(wd * 7 + td);
    }
    __syncthreads();

    float scale = expf(fminf(logit_scale[h], 4.6051702f));
    float* sc = scb + w * 1372;
    float* qT = qTb + w * 128;
    const float* rpbh = d_rpb + (size_t)h * NTOK * NTOK;
    int b = b_ >> 6;

    for (int g = w; g * 4 < NTOK; g += 8) {
        int row0 = g * 4;
        int nr = NTOK - row0; if (nr > 4) nr = 4;
        int rowv[4], outl[4], rvr[4];
        #pragma unroll
        for (int r = 0; r < 4; r++) {
            int row = row0 + (r < nr ? r : 0);
            rowv[r] = row;
            float qv = d_q[base + row * 32 + lane];
            float ss = qv * qv;
            #pragma unroll
            for (int o = 16; o; o >>= 1) ss += __shfl_xor_sync(0xffffffffu, ss, o);
            qv = qv * (1.0f / fmaxf(sqrtf(ss), 1e-12f)) * scale;
            qT[lane * 4 + r] = qv;
            int th = row / 49; int rem = row - th * 49;
            int tw = rem / 7;  int td = rem - tw * 7;
            int hh = (wh * 7 + th + 3) % 28;
            int wc = (ww * 7 + tw + 3) % 28;
            int dc = (wd * 7 + td + 3) % 28;
            outl[r] = b * LTOK + (hh * 28 + wc) * 28 + dc;
            rvr[r] = rv[row];
        }
        __syncwarp();

        // scores S[r][j] = qn[r] . knT[:,j] * scale  + rpb + mask
        for (int jt = 0; jt < 11; jt++) {
            int j = jt * 32 + lane;
            int jc = j < NTOK ? j : NTOK - 1;
            float a0 = 0, a1 = 0, a2 = 0, a3 = 0;
            #pragma unroll
            for (int d = 0; d < 32; d++) {
                float kv = kT[d * NTOK + jc];
                float4 q4 = *(const float4*)&qT[d * 4];
                a0 = fmaf(q4.x, kv, a0); a1 = fmaf(q4.y, kv, a1);
                a2 = fmaf(q4.z, kv, a2); a3 = fmaf(q4.w, kv, a3);
            }
            if (j < NTOK) {
                int rj = rv[j];
                a0 += rpbh[(size_t)rowv[0] * NTOK + j] + (rvr[0] != rj ? -100.0f : 0.0f);
                a1 += rpbh[(size_t)rowv[1] * NTOK + j] + (rvr[1] != rj ? -100.0f : 0.0f);
                a2 += rpbh[(size_t)rowv[2] * NTOK + j] + (rvr[2] != rj ? -100.0f : 0.0f);
                a3 += rpbh[(size_t)rowv[3] * NTOK + j] + (rvr[3] != rj ? -100.0f : 0.0f);
                *(float4*)&sc[j * 4] = make_float4(a0, a1, a2, a3);
            }
        }
        __syncwarp();

        // softmax per row
        float rsum[4];
        #pragma unroll
        for (int r = 0; r < 4; r++) {
            float mx = -1e30f;
            for (int jt = 0; jt < 11; jt++) {
                int j = jt * 32 + lane;
                if (j < NTOK) mx = fmaxf(mx, sc[j * 4 + r]);
            }
            #pragma unroll
            for (int o = 16; o; o >>= 1) mx = fmaxf(mx, __shfl_xor_sync(0xffffffffu, mx, o));
            float s = 0;
            for (int jt = 0; jt < 11; jt++) {
                int j = jt * 32 + lane;
                if (j < NTOK) {
                    float e = expf(sc[j * 4 + r] - mx);
                    sc[j * 4 + r] = e;
                    s += e;
                }
            }
            #pragma unroll
            for (int o = 16; o; o >>= 1) s += __shfl_xor_sync(0xffffffffu, s, o);
            rsum[r] = 1.0f / s;
        }
        __syncwarp();

        // PV
        float o0 = 0, o1 = 0, o2 = 0, o3 = 0;
        #pragma unroll 7
        for (int j = 0; j < NTOK; j++) {
            float4 p4 = *(const float4*)&sc[j * 4];
            float vvv = vs[j * 32 + lane];
            o0 = fmaf(p4.x, vvv, o0); o1 = fmaf(p4.y, vvv, o1);
            o2 = fmaf(p4.z, vvv, o2); o3 = fmaf(p4.w, vvv, o3);
        }
        float oo[4] = {o0, o1, o2, o3};
        for (int r = 0; r < nr; r++)
            d_attn[(size_t)outl[r] * CDIM + h * 32 + lane] = oo[r] * rsum[r];
    }
}

// ---------------- LayerNorm(inp)*g+b + res ----------------
__global__ void __launch_bounds__(256) ln_res_kernel(const float* __restrict__ inp,
                                                     const float* __restrict__ res,
                                                     const float* __restrict__ g,
                                                     const float* __restrict__ bb,
                                                     float* __restrict__ out) {
    int row = blockIdx.x * 8 + (threadIdx.x >> 5);
    int lane = threadIdx.x & 31;
    const float* p = inp + (size_t)row * CDIM;
    float v[6]; float s = 0, s2 = 0;
    #pragma unroll
    for (int i = 0; i < 6; i++) {
        float x = p[lane + 32 * i];
        v[i] = x; s += x; s2 = fmaf(x, x, s2);
    }
    #pragma unroll
    for (int o = 16; o; o >>= 1) {
        s  += __shfl_xor_sync(0xffffffffu, s, o);
        s2 += __shfl_xor_sync(0xffffffffu, s2, o);
    }
    float mean = s * (1.0f / 192.0f);
    float var = s2 * (1.0f / 192.0f) - mean * mean;
    float rstd = rsqrtf(var + 1e-5f);
    const float* rr = res + (size_t)row * CDIM;
    float* oo = out + (size_t)row * CDIM;
    #pragma unroll
    for (int i = 0; i < 6; i++) {
        int c = lane + 32 * i;
        oo[c] = rr[c] + (v[i] - mean) * rstd * g[c] + bb[c];
    }
}

// ---------------- launch ----------------
extern "C" void kernel_launch(void* const* d_in, const int* in_sizes, int n_in,
                              void* d_out, int out_size) {
    const float* x       = (const float*)d_in[0];
    const float* qkv_w   = (const float*)d_in[1];
    const float* q_bias  = (const float*)d_in[2];
    const float* v_bias  = (const float*)d_in[3];
    const float* lscale  = (const float*)d_in[4];
    const float* cpb_w1  = (const float*)d_in[5];
    const float* cpb_b1  = (const float*)d_in[6];
    const float* cpb_w2  = (const float*)d_in[7];
    const float* proj_w  = (const float*)d_in[8];
    const float* proj_b  = (const float*)d_in[9];
    const float* n1g     = (const float*)d_in[10];
    const float* n1b     = (const float*)d_in[11];
    const float* fc1_w   = (const float*)d_in[12];
    const float* fc1_b   = (const float*)d_in[13];
    const float* fc2_w   = (const float*)d_in[14];
    const float* fc2_b   = (const float*)d_in[15];
    const float* n2g     = (const float*)d_in[16];
    const float* n2b     = (const float*)d_in[17];
    float* out = (float*)d_out;

    void *p_attn, *p_tmp, *p_x1, *p_hid;
    cudaGetSymbolAddress(&p_attn, d_attn);
    cudaGetSymbolAddress(&p_tmp, d_tmp);
    cudaGetSymbolAddress(&p_x1, d_x1);
    cudaGetSymbolAddress(&p_hid, d_hid);

    cpb_kernel<<<275, 256>>>(cpb_w1, cpb_b1, cpb_w2);
    rpb_kernel<<<2758, 256>>>();

    // QKV: gathered-A GEMM, scatter epilogue
    gemm_k<true, 2><<<dim3(9, 686), 256>>>(x, qkv_w, nullptr, nullptr, 192, 576, q_bias, v_bias);

    cudaFuncSetAttribute(attn_kernel, cudaFuncAttributeMaxDynamicSharedMemorySize, 137184);
    attn_kernel<<<768, 256, 137184>>>(lscale);

    // proj
    gemm_k<false, 0><<<dim3(3, 686), 256>>>((const float*)p_attn, proj_w, proj_b,
                                            (float*)p_tmp, 192, 192, nullptr, nullptr);
    // x1 = x + LN(proj)
    ln_res_kernel<<<5488, 256>>>((const float*)p_tmp, x, n1g, n1b, (float*)p_x1);
    // fc1 + GELU
    gemm_k<false, 1><<<dim3(12, 686), 256>>>((const float*)p_x1, fc1_w, fc1_b,
                                             (float*)p_hid, 192, 768, nullptr, nullptr);
    // fc2
    gemm_k<false, 0><<<dim3(3, 686), 256>>>((const float*)p_hid, fc2_w, fc2_b,
                                            (float*)p_tmp, 768, 192, nullptr, nullptr);
    // out = x1 + LN(fc2)
    ln_res_kernel<<<5488, 256>>>((const float*)p_tmp, (const float*)p_x1, n2g, n2b, out);
}